// round 3
// baseline (speedup 1.0000x reference)
#include <cuda_runtime.h>
#include <cuda_bf16.h>
#include <math.h>

typedef unsigned long long u64;

#define N_OSC 50
#define N_PER 40
#define STEPS 100
#define BATCH 8192
#define NPAIR 25              // oscillator pairs
#define NUNITS (256 * NPAIR)  // 256 batch-groups of 32 x 25 osc-pairs = 6400

// ---------------- packed f32x2 helpers ----------------
#define FMA2(d, a, b, c) \
    asm("fma.rn.f32x2 %0, %1, %2, %3;" : "=l"(d) : "l"(a), "l"(b), "l"(c))
#define PACK2(v, lo, hi) \
    asm("mov.b64 %0, {%1, %2};" : "=l"(v) : "f"(lo), "f"(hi))
#define UNPACK2(lo, hi, v) \
    asm("mov.b64 {%0, %1}, %2;" : "=f"(lo), "=f"(hi) : "l"(v))

// ---------------- device scratch (no allocs allowed) ----------------
__device__ float g_x3[BATCH * 100];            // o0 initial states, [b][100]
__device__ float g_direct[BATCH];              // direct torque term per batch
__device__ float g_cpack[NPAIR * N_PER * 12];  // packed per-(osc-pair, n) constants
__device__ float g_tqp[NPAIR * STEPS * BATCH]; // per-osc-pair torque partials
__device__ float g_tq[STEPS * BATCH];          // reduced torque (pre direct)
__device__ unsigned int g_ticket;

// ============================================================
// K0: pack constants + reset ticket
// layout per (op, n): {e0A,e0B,e1A,e1B, obA,obB,d0A,d0B, d1A,d1B,wA,wB}
// ============================================================
__global__ void prep_kernel(const float* __restrict__ enc,
                            const float* __restrict__ obias,
                            const float* __restrict__ dec,
                            const float* __restrict__ fc4_w) {
    int i = blockIdx.x * blockDim.x + threadIdx.x;
    if (i == 0) g_ticket = 0u;
    if (i < NPAIR * N_PER) {
        int op = i / N_PER, n = i % N_PER;
        int oA = 2 * op, oB = 2 * op + 1;
        float* dst = g_cpack + (size_t)i * 12;
        dst[0]  = enc[oA * 80 + n * 2 + 0];
        dst[1]  = enc[oB * 80 + n * 2 + 0];
        dst[2]  = enc[oA * 80 + n * 2 + 1];
        dst[3]  = enc[oB * 80 + n * 2 + 1];
        dst[4]  = obias[oA * 40 + n];
        dst[5]  = obias[oB * 40 + n];
        dst[6]  = dec[oA * 80 + n];        // dec[oA][0][n]
        dst[7]  = dec[oB * 80 + n];
        dst[8]  = dec[oA * 80 + 40 + n];   // dec[oA][1][n]
        dst[9]  = dec[oB * 80 + 40 + n];
        dst[10] = fc4_w[oA * 40 + n];
        dst[11] = fc4_w[oB * 40 + n];
    }
}

// ============================================================
// K1: fused MLP per batch row: h -> (direct, h2 -> x3)
// block = 128 threads = one batch row
// ============================================================
__global__ __launch_bounds__(128) void mlp_kernel(
    const float* __restrict__ x,
    const float* __restrict__ fc1_w, const float* __restrict__ fc1_b,
    const float* __restrict__ fc2_w, const float* __restrict__ fc2_b,
    const float* __restrict__ fc3_w, const float* __restrict__ fc3_b,
    const float* __restrict__ fcd_w, const float* __restrict__ fcd_b) {
    __shared__ float4 s_h4[32];
    __shared__ float4 s_h24[32];
    const float* s_h  = (const float*)s_h4;

    int b = blockIdx.x;
    int j = threadIdx.x;
    float x0 = x[b * 2 + 0], x1 = x[b * 2 + 1];

    // h = relu(x @ fc1_w.T + fc1_b)
    float h = fmaxf(fmaf(x0, fc1_w[j * 2 + 0], fmaf(x1, fc1_w[j * 2 + 1], fc1_b[j])), 0.f);
    ((float*)s_h4)[j] = h;
    __syncthreads();

    // h2 = relu(h @ fc2_w.T + fc2_b)
    float acc = fc2_b[j];
    const float4* w4 = (const float4*)(fc2_w + (size_t)j * 128);
#pragma unroll
    for (int k = 0; k < 32; ++k) {
        float4 w = __ldg(w4 + k);
        float4 hh = s_h4[k];
        acc = fmaf(w.x, hh.x, acc);
        acc = fmaf(w.y, hh.y, acc);
        acc = fmaf(w.z, hh.z, acc);
        acc = fmaf(w.w, hh.w, acc);
    }
    ((float*)s_h24)[j] = fmaxf(acc, 0.f);

    // direct = h @ fcd_w.T + fcd_b  (warp 0; s_h is final)
    if (j < 32) {
        float p = s_h[j] * fcd_w[j] + s_h[j + 32] * fcd_w[j + 32] +
                  s_h[j + 64] * fcd_w[j + 64] + s_h[j + 96] * fcd_w[j + 96];
#pragma unroll
        for (int o = 16; o > 0; o >>= 1) p += __shfl_down_sync(0xffffffffu, p, o);
        if (j == 0) g_direct[b] = p + fcd_b[0];
    }
    __syncthreads();

    // x3 = h2 @ fc3_w.T + fc3_b   (100 outputs)
    if (j < 100) {
        float a2 = fc3_b[j];
        const float4* w34 = (const float4*)(fc3_w + (size_t)j * 128);
#pragma unroll
        for (int k = 0; k < 32; ++k) {
            float4 w = __ldg(w34 + k);
            float4 hh = s_h24[k];
            a2 = fmaf(w.x, hh.x, a2);
            a2 = fmaf(w.y, hh.y, a2);
            a2 = fmaf(w.z, hh.z, a2);
            a2 = fmaf(w.w, hh.w, a2);
        }
        g_x3[(size_t)b * 100 + j] = a2;
    }
}

// ============================================================
// K2: oscillator scan. Unit = (batch-group of 32, osc-pair).
// lane = batch element; f32x2 packs the 2 oscillators of the pair.
//
// R3 changes vs R2:
//  - launch_bounds(256,3) + grid 444: 3 blocks/SM -> 6 warps/SMSP
//    (better LDS-latency hiding) and 3552 warp slots so the 6400
//    ticket units distribute at 90% utilization (was 67%).
//  - unroll 4 keeps live constants ~48 regs so the 85-reg cap
//    does not spill.
// ============================================================
__global__ __launch_bounds__(256, 3) void osc_kernel() {
    __shared__ float s_c[NPAIR * N_PER * 12];  // 48000 B
    for (int i = threadIdx.x; i < NPAIR * N_PER * 3; i += 256)
        ((float4*)s_c)[i] = ((const float4*)g_cpack)[i];
    __syncthreads();

    const int lane = threadIdx.x & 31;
    u64 dt2;
    PACK2(dt2, 0.01f, 0.01f);

    for (;;) {
        unsigned u = 0;
        if (lane == 0) u = atomicAdd(&g_ticket, 1u);
        u = __shfl_sync(0xffffffffu, u, 0);
        if (u >= NUNITS) break;

        const unsigned op = u % NPAIR;
        const unsigned bg = u / NPAIR;
        const int b = bg * 32 + lane;

        // initial o state: x3[b][4op .. 4op+3] = {oxA, oyA, oxB, oyB}
        float4 o0 = __ldg((const float4*)(g_x3 + (size_t)b * 100 + op * 4));
        u64 ox2, oy2;
        PACK2(ox2, o0.x, o0.z);
        PACK2(oy2, o0.y, o0.w);

        const ulonglong2* cp = ((const ulonglong2*)s_c) + (size_t)op * 120;
        float* tq_out = g_tqp + (size_t)op * (STEPS * BATCH) + b;

        for (int t = 0; t < STEPS; ++t) {
            u64 dx = 0ull, dy = 0ull, tq = 0ull;
#pragma unroll 4
            for (int n = 0; n < N_PER; ++n) {
                ulonglong2 c0 = cp[n * 3 + 0];  // {e0A,e0B | e1A,e1B}
                ulonglong2 c1 = cp[n * 3 + 1];  // {obA,obB | d0A,d0B}
                ulonglong2 c2 = cp[n * 3 + 2];  // {d1A,d1B | wA,wB}
                u64 t2;
                FMA2(t2, ox2, c0.x, c1.x);
                FMA2(t2, oy2, c0.y, t2);
                float aL, aH;
                UNPACK2(aL, aH, t2);
                aL = fmaxf(aL, 0.f);
                aH = fmaxf(aH, 0.f);
                u64 a2;
                PACK2(a2, aL, aH);
                FMA2(dx, c1.y, a2, dx);
                FMA2(dy, c2.x, a2, dy);
                FMA2(tq, c2.y, a2, tq);
            }
            FMA2(ox2, dt2, dx, ox2);
            FMA2(oy2, dt2, dy, oy2);
            float tl, th;
            UNPACK2(tl, th, tq);
            tq_out[t * BATCH] = tl + th;   // deterministic per-unit slot
        }
    }
}

// ============================================================
// K3: reduce 25 osc-pair partials -> g_tq  (coalesced, BW-bound)
// ============================================================
__global__ void reduce_kernel() {
    int i = blockIdx.x * blockDim.x + threadIdx.x;  // < STEPS*BATCH
    float s = 0.f;
#pragma unroll
    for (int p = 0; p < NPAIR; ++p) s += g_tqp[(size_t)p * (STEPS * BATCH) + i];
    g_tq[i] = s;
}

// ============================================================
// K4: pendulum scan + output writes
// out layout: l_states [100][8192][2] then torques [100][8192]
// ============================================================
__global__ void scan_kernel(const float* __restrict__ x,
                            const float* __restrict__ fc4_b,
                            float* __restrict__ out) {
    int b = blockIdx.x * blockDim.x + threadIdx.x;  // < BATCH
    float theta = x[b * 2 + 0];
    float omega = 0.f;
    const float dir = g_direct[b] + fc4_b[0];
    float2* outL = (float2*)out;                    // (t*BATCH+b) float2 each
    float* outT = out + STEPS * BATCH * 2;
    for (int t = 0; t < STEPS; ++t) {
        float tau = g_tq[t * BATCH + b] + dir;
        float alpha = tau - sinf(theta) - 0.1f * omega;  // M_G_LC=1, I=1
        float th2 = theta + 0.01f * omega;
        float om2 = omega + 0.01f * alpha;
        outL[t * BATCH + b] = make_float2(th2, om2);
        outT[t * BATCH + b] = tau;
        theta = th2;
        omega = om2;
    }
}

// ============================================================
extern "C" void kernel_launch(void* const* d_in, const int* in_sizes, int n_in,
                              void* d_out, int out_size) {
    const float* x     = (const float*)d_in[0];
    const float* fc1_w = (const float*)d_in[1];
    const float* fc1_b = (const float*)d_in[2];
    const float* fc2_w = (const float*)d_in[3];
    const float* fc2_b = (const float*)d_in[4];
    const float* fc3_w = (const float*)d_in[5];
    const float* fc3_b = (const float*)d_in[6];
    const float* fcd_w = (const float*)d_in[7];
    const float* fcd_b = (const float*)d_in[8];
    const float* enc   = (const float*)d_in[9];
    const float* obias = (const float*)d_in[10];
    const float* dec   = (const float*)d_in[11];
    const float* fc4_w = (const float*)d_in[12];
    const float* fc4_b = (const float*)d_in[13];
    float* out = (float*)d_out;

    prep_kernel<<<8, 128>>>(enc, obias, dec, fc4_w);
    mlp_kernel<<<BATCH, 128>>>(x, fc1_w, fc1_b, fc2_w, fc2_b, fc3_w, fc3_b, fcd_w, fcd_b);
    osc_kernel<<<148 * 3, 256>>>();
    reduce_kernel<<<(STEPS * BATCH) / 256, 256>>>();
    scan_kernel<<<BATCH / 256, 256>>>(x, fc4_b, out);
}

// round 4
// speedup vs baseline: 1.0677x; 1.0677x over previous
#include <cuda_runtime.h>
#include <cuda_bf16.h>
#include <math.h>

typedef unsigned long long u64;

#define N_OSC 50
#define N_PER 40
#define STEPS 100
#define BATCH 8192
#define NPAIR 25               // oscillator pairs
#define NUNITS (128 * NPAIR)   // 128 batch-groups of 64 x 25 osc-pairs = 3200

// ---------------- packed f32x2 helpers ----------------
#define FMA2(d, a, b, c) \
    asm("fma.rn.f32x2 %0, %1, %2, %3;" : "=l"(d) : "l"(a), "l"(b), "l"(c))
#define PACK2(v, lo, hi) \
    asm("mov.b64 %0, {%1, %2};" : "=l"(v) : "f"(lo), "f"(hi))
#define UNPACK2(lo, hi, v) \
    asm("mov.b64 {%0, %1}, %2;" : "=f"(lo), "=f"(hi) : "l"(v))

// ---------------- device scratch (no allocs allowed) ----------------
__device__ float g_x3[BATCH * 100];            // o0 initial states, [b][100]
__device__ float g_direct[BATCH];              // direct torque term per batch (pre fc4_b)
__device__ float g_dir[BATCH];                 // direct + fc4_b
__device__ float g_cpack[NPAIR * N_PER * 12];  // packed per-(osc-pair, n) constants
__device__ float g_tqp[NPAIR * STEPS * BATCH]; // per-osc-pair torque partials
__device__ unsigned int g_ticket;

// ============================================================
// K0 (pos 1): pack constants + reset ticket
// layout per (op, n): {e0A,e0B,e1A,e1B, obA,obB,d0A,d0B, d1A,d1B,wA,wB}
// ============================================================
__global__ void prep_kernel(const float* __restrict__ enc,
                            const float* __restrict__ obias,
                            const float* __restrict__ dec,
                            const float* __restrict__ fc4_w) {
    int i = blockIdx.x * blockDim.x + threadIdx.x;
    if (i == 0) g_ticket = 0u;
    if (i < NPAIR * N_PER) {
        int op = i / N_PER, n = i % N_PER;
        int oA = 2 * op, oB = 2 * op + 1;
        float* dst = g_cpack + (size_t)i * 12;
        dst[0]  = enc[oA * 80 + n * 2 + 0];
        dst[1]  = enc[oB * 80 + n * 2 + 0];
        dst[2]  = enc[oA * 80 + n * 2 + 1];
        dst[3]  = enc[oB * 80 + n * 2 + 1];
        dst[4]  = obias[oA * 40 + n];
        dst[5]  = obias[oB * 40 + n];
        dst[6]  = dec[oA * 80 + n];        // dec[oA][0][n]
        dst[7]  = dec[oB * 80 + n];
        dst[8]  = dec[oA * 80 + 40 + n];   // dec[oA][1][n]
        dst[9]  = dec[oB * 80 + 40 + n];
        dst[10] = fc4_w[oA * 40 + n];
        dst[11] = fc4_w[oB * 40 + n];
    }
}

// ============================================================
// K1 (pos 2): fused MLP per batch row: h -> (direct, h2 -> x3)
// ============================================================
__global__ __launch_bounds__(128) void mlp_kernel(
    const float* __restrict__ x,
    const float* __restrict__ fc1_w, const float* __restrict__ fc1_b,
    const float* __restrict__ fc2_w, const float* __restrict__ fc2_b,
    const float* __restrict__ fc3_w, const float* __restrict__ fc3_b,
    const float* __restrict__ fcd_w, const float* __restrict__ fcd_b) {
    __shared__ float4 s_h4[32];
    __shared__ float4 s_h24[32];
    const float* s_h  = (const float*)s_h4;

    int b = blockIdx.x;
    int j = threadIdx.x;
    float x0 = x[b * 2 + 0], x1 = x[b * 2 + 1];

    float h = fmaxf(fmaf(x0, fc1_w[j * 2 + 0], fmaf(x1, fc1_w[j * 2 + 1], fc1_b[j])), 0.f);
    ((float*)s_h4)[j] = h;
    __syncthreads();

    float acc = fc2_b[j];
    const float4* w4 = (const float4*)(fc2_w + (size_t)j * 128);
#pragma unroll
    for (int k = 0; k < 32; ++k) {
        float4 w = __ldg(w4 + k);
        float4 hh = s_h4[k];
        acc = fmaf(w.x, hh.x, acc);
        acc = fmaf(w.y, hh.y, acc);
        acc = fmaf(w.z, hh.z, acc);
        acc = fmaf(w.w, hh.w, acc);
    }
    ((float*)s_h24)[j] = fmaxf(acc, 0.f);

    if (j < 32) {
        float p = s_h[j] * fcd_w[j] + s_h[j + 32] * fcd_w[j + 32] +
                  s_h[j + 64] * fcd_w[j + 64] + s_h[j + 96] * fcd_w[j + 96];
#pragma unroll
        for (int o = 16; o > 0; o >>= 1) p += __shfl_down_sync(0xffffffffu, p, o);
        if (j == 0) g_direct[b] = p + fcd_b[0];
    }
    __syncthreads();

    if (j < 100) {
        float a2 = fc3_b[j];
        const float4* w34 = (const float4*)(fc3_w + (size_t)j * 128);
#pragma unroll
        for (int k = 0; k < 32; ++k) {
            float4 w = __ldg(w34 + k);
            float4 hh = s_h24[k];
            a2 = fmaf(w.x, hh.x, a2);
            a2 = fmaf(w.y, hh.y, a2);
            a2 = fmaf(w.z, hh.z, a2);
            a2 = fmaf(w.w, hh.w, a2);
        }
        g_x3[(size_t)b * 100 + j] = a2;
    }
}

// ============================================================
// K2 (pos 3): tiny kernel: dir = direct + fc4_b  (also shifts the
// ncu capture slot so osc_kernel lands at position 4)
// ============================================================
__global__ void dir_kernel(const float* __restrict__ fc4_b) {
    int b = blockIdx.x * blockDim.x + threadIdx.x;
    if (b < BATCH) g_dir[b] = g_direct[b] + fc4_b[0];
}

// ============================================================
// K3 (pos 4): oscillator scan. Unit = (batch-group of 64, osc-pair).
// Each thread handles TWO batch elements (b0 = bg*64+lane, b1 = b0+32);
// the f32x2 lanes pack the 2 oscillators of a pair. This halves the
// shared-memory (constants) traffic per MAC — the occupancy-insensitive
// structural floor identified in R3.
// 3200 units, grid 444 x occ3 = 3552 warp slots -> every warp <= 1 unit.
// ============================================================
__global__ __launch_bounds__(256, 3) void osc_kernel() {
    __shared__ float s_c[NPAIR * N_PER * 12];  // 48000 B
    for (int i = threadIdx.x; i < NPAIR * N_PER * 3; i += 256)
        ((float4*)s_c)[i] = ((const float4*)g_cpack)[i];
    __syncthreads();

    const int lane = threadIdx.x & 31;
    u64 dt2;
    PACK2(dt2, 0.01f, 0.01f);

    for (;;) {
        unsigned u = 0;
        if (lane == 0) u = atomicAdd(&g_ticket, 1u);
        u = __shfl_sync(0xffffffffu, u, 0);
        if (u >= NUNITS) break;

        const unsigned op = u % NPAIR;
        const unsigned bg = u / NPAIR;
        const int b0 = bg * 64 + lane;
        const int b1 = b0 + 32;

        float4 oA = __ldg((const float4*)(g_x3 + (size_t)b0 * 100 + op * 4));
        float4 oB = __ldg((const float4*)(g_x3 + (size_t)b1 * 100 + op * 4));
        u64 oxa, oya, oxb, oyb;
        PACK2(oxa, oA.x, oA.z);
        PACK2(oya, oA.y, oA.w);
        PACK2(oxb, oB.x, oB.z);
        PACK2(oyb, oB.y, oB.w);

        const ulonglong2* cp = ((const ulonglong2*)s_c) + (size_t)op * 120;
        float* tq_out = g_tqp + (size_t)op * (STEPS * BATCH) + b0;

        for (int t = 0; t < STEPS; ++t) {
            u64 dxa = 0ull, dya = 0ull, tqa = 0ull;
            u64 dxb = 0ull, dyb = 0ull, tqb = 0ull;
#pragma unroll 2
            for (int n = 0; n < N_PER; ++n) {
                ulonglong2 c0 = cp[n * 3 + 0];  // {e0A,e0B | e1A,e1B}
                ulonglong2 c1 = cp[n * 3 + 1];  // {obA,obB | d0A,d0B}
                ulonglong2 c2 = cp[n * 3 + 2];  // {d1A,d1B | wA,wB}
                u64 ta, tb;
                FMA2(ta, oxa, c0.x, c1.x);
                FMA2(tb, oxb, c0.x, c1.x);
                FMA2(ta, oya, c0.y, ta);
                FMA2(tb, oyb, c0.y, tb);
                float l0, h0, l1, h1;
                UNPACK2(l0, h0, ta);
                UNPACK2(l1, h1, tb);
                l0 = fmaxf(l0, 0.f); h0 = fmaxf(h0, 0.f);
                l1 = fmaxf(l1, 0.f); h1 = fmaxf(h1, 0.f);
                u64 aa, ab;
                PACK2(aa, l0, h0);
                PACK2(ab, l1, h1);
                FMA2(dxa, c1.y, aa, dxa);
                FMA2(dxb, c1.y, ab, dxb);
                FMA2(dya, c2.x, aa, dya);
                FMA2(dyb, c2.x, ab, dyb);
                FMA2(tqa, c2.y, aa, tqa);
                FMA2(tqb, c2.y, ab, tqb);
            }
            FMA2(oxa, dt2, dxa, oxa);
            FMA2(oya, dt2, dya, oya);
            FMA2(oxb, dt2, dxb, oxb);
            FMA2(oyb, dt2, dyb, oyb);
            float sl, sh;
            UNPACK2(sl, sh, tqa);
            float s0 = sl + sh;
            UNPACK2(sl, sh, tqb);
            float s1 = sl + sh;
            tq_out[t * BATCH]      = s0;  // b0 slot
            tq_out[t * BATCH + 32] = s1;  // b1 slot
        }
    }
}

// ============================================================
// K4 (pos 5): fused reduce + pendulum scan + output writes
// out layout: l_states [100][8192][2] then torques [100][8192]
// ============================================================
__global__ void scan_kernel(const float* __restrict__ x,
                            float* __restrict__ out) {
    int b = blockIdx.x * blockDim.x + threadIdx.x;  // < BATCH
    float theta = x[b * 2 + 0];
    float omega = 0.f;
    const float dir = g_dir[b];
    float2* outL = (float2*)out;
    float* outT = out + STEPS * BATCH * 2;
    for (int t = 0; t < STEPS; ++t) {
        float s = 0.f;
        const float* p = g_tqp + (size_t)t * BATCH + b;
#pragma unroll
        for (int q = 0; q < NPAIR; ++q) s += p[(size_t)q * (STEPS * BATCH)];
        float tau = s + dir;
        float alpha = tau - sinf(theta) - 0.1f * omega;  // M_G_LC=1, I=1
        float th2 = theta + 0.01f * omega;
        float om2 = omega + 0.01f * alpha;
        outL[t * BATCH + b] = make_float2(th2, om2);
        outT[t * BATCH + b] = tau;
        theta = th2;
        omega = om2;
    }
}

// ============================================================
extern "C" void kernel_launch(void* const* d_in, const int* in_sizes, int n_in,
                              void* d_out, int out_size) {
    const float* x     = (const float*)d_in[0];
    const float* fc1_w = (const float*)d_in[1];
    const float* fc1_b = (const float*)d_in[2];
    const float* fc2_w = (const float*)d_in[3];
    const float* fc2_b = (const float*)d_in[4];
    const float* fc3_w = (const float*)d_in[5];
    const float* fc3_b = (const float*)d_in[6];
    const float* fcd_w = (const float*)d_in[7];
    const float* fcd_b = (const float*)d_in[8];
    const float* enc   = (const float*)d_in[9];
    const float* obias = (const float*)d_in[10];
    const float* dec   = (const float*)d_in[11];
    const float* fc4_w = (const float*)d_in[12];
    const float* fc4_b = (const float*)d_in[13];
    float* out = (float*)d_out;

    prep_kernel<<<8, 128>>>(enc, obias, dec, fc4_w);
    mlp_kernel<<<BATCH, 128>>>(x, fc1_w, fc1_b, fc2_w, fc2_b, fc3_w, fc3_b, fcd_w, fcd_b);
    dir_kernel<<<BATCH / 256, 256>>>(fc4_b);
    osc_kernel<<<444, 256>>>();
    scan_kernel<<<BATCH / 256, 256>>>(x, out);
}

// round 5
// speedup vs baseline: 1.1079x; 1.0377x over previous
#include <cuda_runtime.h>
#include <cuda_bf16.h>
#include <math.h>

typedef unsigned long long u64;

#define N_OSC 50
#define N_PER 40
#define STEPS 100
#define BATCH 8192
#define NPAIR 25               // oscillator pairs
#define NUNITS (128 * NPAIR)   // 128 batch-groups of 64 x 25 osc-pairs = 3200

// ---------------- packed f32x2 helpers ----------------
#define FMA2(d, a, b, c) \
    asm("fma.rn.f32x2 %0, %1, %2, %3;" : "=l"(d) : "l"(a), "l"(b), "l"(c))
#define PACK2(v, lo, hi) \
    asm("mov.b64 %0, {%1, %2};" : "=l"(v) : "f"(lo), "f"(hi))
#define UNPACK2(lo, hi, v) \
    asm("mov.b64 {%0, %1}, %2;" : "=f"(lo), "=f"(hi) : "l"(v))

// ---------------- device scratch (no allocs allowed) ----------------
__device__ float g_x3[BATCH * 100];            // o0 initial states, [b][100]
__device__ float g_direct[BATCH];              // direct torque term per batch
__device__ float g_dir[BATCH];                 // direct + fc4_b
__device__ float g_cpack[NPAIR * N_PER * 12];  // packed per-(osc-pair, n) constants
__device__ float g_fc2t[128 * 128];            // fc2_w transposed (k-major)
__device__ float g_fc3t[128 * 128];            // fc3_w transposed, zero-padded rows
__device__ float g_tqp[NPAIR * STEPS * BATCH]; // per-osc-pair torque partials
__device__ unsigned int g_ticket;

// ============================================================
// K0 (pos 1): pack constants, transpose weights, reset ticket
// ============================================================
__global__ void prep_kernel(const float* __restrict__ enc,
                            const float* __restrict__ obias,
                            const float* __restrict__ dec,
                            const float* __restrict__ fc4_w,
                            const float* __restrict__ fc2_w,
                            const float* __restrict__ fc3_w) {
    int i = blockIdx.x * blockDim.x + threadIdx.x;
    if (i == 0) g_ticket = 0u;
    if (i < 16384) {
        int k = i / 128, j = i % 128;
        g_fc2t[i] = fc2_w[j * 128 + k];
        g_fc3t[i] = (j < 100) ? fc3_w[j * 128 + k] : 0.f;
    }
    if (i < NPAIR * N_PER) {
        int op = i / N_PER, n = i % N_PER;
        int oA = 2 * op, oB = 2 * op + 1;
        float* dst = g_cpack + (size_t)i * 12;
        dst[0]  = enc[oA * 80 + n * 2 + 0];
        dst[1]  = enc[oB * 80 + n * 2 + 0];
        dst[2]  = enc[oA * 80 + n * 2 + 1];
        dst[3]  = enc[oB * 80 + n * 2 + 1];
        dst[4]  = obias[oA * 40 + n];
        dst[5]  = obias[oB * 40 + n];
        dst[6]  = dec[oA * 80 + n];        // dec[oA][0][n]
        dst[7]  = dec[oB * 80 + n];
        dst[8]  = dec[oA * 80 + 40 + n];   // dec[oA][1][n]
        dst[9]  = dec[oB * 80 + 40 + n];
        dst[10] = fc4_w[oA * 40 + n];
        dst[11] = fc4_w[oB * 40 + n];
    }
}

// ============================================================
// K1 (pos 2): MLP v2. Block = 128 threads = 8 batch rows.
// All weights k-major (coalesced LDG.64), all MACs f32x2.
// smem h layout: s_h[j*2+rg] = {h(rows 4rg,4rg+1), h(rows 4rg+2,4rg+3)}
// ============================================================
__global__ __launch_bounds__(128) void mlp_kernel(
    const float* __restrict__ x,
    const float* __restrict__ fc1_w, const float* __restrict__ fc1_b,
    const float* __restrict__ fc2_b, const float* __restrict__ fc3_b,
    const float* __restrict__ fcd_w, const float* __restrict__ fcd_b) {
    __shared__ ulonglong2 s_h[256];
    __shared__ ulonglong2 s_h2[256];
    __shared__ float s_red[4][8];

    const int tid = threadIdx.x;
    const int base = blockIdx.x * 8;

    // ---- pack x for 8 rows ----
    u64 x0p[4], x1p[4];
#pragma unroll
    for (int p = 0; p < 4; ++p) {
        float2 ra = ((const float2*)x)[base + 2 * p];
        float2 rb = ((const float2*)x)[base + 2 * p + 1];
        PACK2(x0p[p], ra.x, rb.x);
        PACK2(x1p[p], ra.y, rb.y);
    }

    // ---- fc1: h_j for 8 rows ----
    float w0 = fc1_w[tid * 2 + 0], w1 = fc1_w[tid * 2 + 1], b1v = fc1_b[tid];
    u64 w02, w12, b12;
    PACK2(w02, w0, w0);
    PACK2(w12, w1, w1);
    PACK2(b12, b1v, b1v);
    u64 h[4];
    float hr[8];
#pragma unroll
    for (int p = 0; p < 4; ++p) {
        u64 t;
        FMA2(t, w02, x0p[p], b12);
        FMA2(t, w12, x1p[p], t);
        float lo, hi;
        UNPACK2(lo, hi, t);
        lo = fmaxf(lo, 0.f);
        hi = fmaxf(hi, 0.f);
        hr[2 * p] = lo;
        hr[2 * p + 1] = hi;
        PACK2(h[p], lo, hi);
    }
    s_h[tid * 2 + 0] = make_ulonglong2(h[0], h[1]);
    s_h[tid * 2 + 1] = make_ulonglong2(h[2], h[3]);

    // ---- fcd: direct term, deterministic tree reduce ----
    {
        float wd = fcd_w[tid];
        int lane = tid & 31, wrp = tid >> 5;
#pragma unroll
        for (int r = 0; r < 8; ++r) {
            float pr = hr[r] * wd;
#pragma unroll
            for (int o = 16; o > 0; o >>= 1) pr += __shfl_down_sync(0xffffffffu, pr, o);
            if (lane == 0) s_red[wrp][r] = pr;
        }
    }
    __syncthreads();
    if (tid < 8)
        g_direct[base + tid] =
            s_red[0][tid] + s_red[1][tid] + s_red[2][tid] + s_red[3][tid] + fcd_b[0];

    // ---- fc2: 2 outputs x 4 rows per thread ----
    const int j0 = (tid & 63) * 2;
    const int rg = tid >> 6;
    u64 a00, a01, a10, a11;
    {
        float ba = fc2_b[j0], bb = fc2_b[j0 + 1];
        PACK2(a00, ba, ba);
        a01 = a00;
        PACK2(a10, bb, bb);
        a11 = a10;
    }
#pragma unroll 4
    for (int k = 0; k < 128; ++k) {
        float2 w = __ldg(((const float2*)(g_fc2t + k * 128)) + (tid & 63));
        u64 wa, wb;
        PACK2(wa, w.x, w.x);
        PACK2(wb, w.y, w.y);
        ulonglong2 hh = s_h[k * 2 + rg];
        FMA2(a00, wa, hh.x, a00);
        FMA2(a01, wa, hh.y, a01);
        FMA2(a10, wb, hh.x, a10);
        FMA2(a11, wb, hh.y, a11);
    }
    // relu
    {
        float l, hf;
        UNPACK2(l, hf, a00); l = fmaxf(l, 0.f); hf = fmaxf(hf, 0.f); PACK2(a00, l, hf);
        UNPACK2(l, hf, a01); l = fmaxf(l, 0.f); hf = fmaxf(hf, 0.f); PACK2(a01, l, hf);
        UNPACK2(l, hf, a10); l = fmaxf(l, 0.f); hf = fmaxf(hf, 0.f); PACK2(a10, l, hf);
        UNPACK2(l, hf, a11); l = fmaxf(l, 0.f); hf = fmaxf(hf, 0.f); PACK2(a11, l, hf);
    }
    s_h2[j0 * 2 + rg] = make_ulonglong2(a00, a01);
    s_h2[(j0 + 1) * 2 + rg] = make_ulonglong2(a10, a11);
    __syncthreads();

    // ---- fc3: same structure, zero-padded weights ----
    u64 c00, c01, c10, c11;
    {
        float ba = (j0 < 100) ? fc3_b[j0] : 0.f;
        float bb = (j0 + 1 < 100) ? fc3_b[j0 + 1] : 0.f;
        PACK2(c00, ba, ba);
        c01 = c00;
        PACK2(c10, bb, bb);
        c11 = c10;
    }
#pragma unroll 4
    for (int k = 0; k < 128; ++k) {
        float2 w = __ldg(((const float2*)(g_fc3t + k * 128)) + (tid & 63));
        u64 wa, wb;
        PACK2(wa, w.x, w.x);
        PACK2(wb, w.y, w.y);
        ulonglong2 hh = s_h2[k * 2 + rg];
        FMA2(c00, wa, hh.x, c00);
        FMA2(c01, wa, hh.y, c01);
        FMA2(c10, wb, hh.x, c10);
        FMA2(c11, wb, hh.y, c11);
    }
    // store x3
    {
        float r0, r1, r2, r3;
        if (j0 < 100) {
            UNPACK2(r0, r1, c00);
            UNPACK2(r2, r3, c01);
            g_x3[(size_t)(base + 4 * rg + 0) * 100 + j0] = r0;
            g_x3[(size_t)(base + 4 * rg + 1) * 100 + j0] = r1;
            g_x3[(size_t)(base + 4 * rg + 2) * 100 + j0] = r2;
            g_x3[(size_t)(base + 4 * rg + 3) * 100 + j0] = r3;
        }
        if (j0 + 1 < 100) {
            UNPACK2(r0, r1, c10);
            UNPACK2(r2, r3, c11);
            g_x3[(size_t)(base + 4 * rg + 0) * 100 + j0 + 1] = r0;
            g_x3[(size_t)(base + 4 * rg + 1) * 100 + j0 + 1] = r1;
            g_x3[(size_t)(base + 4 * rg + 2) * 100 + j0 + 1] = r2;
            g_x3[(size_t)(base + 4 * rg + 3) * 100 + j0 + 1] = r3;
        }
    }
}

// ============================================================
// K2 (pos 3): dir = direct + fc4_b (keeps osc at ncu position 4)
// ============================================================
__global__ void dir_kernel(const float* __restrict__ fc4_b) {
    int b = blockIdx.x * blockDim.x + threadIdx.x;
    if (b < BATCH) g_dir[b] = g_direct[b] + fc4_b[0];
}

// ============================================================
// K3 (pos 4): oscillator scan. Unit = (batch-group of 64, osc-pair).
// launch_bounds(256,4) + smem carveout 100% -> 4 blocks/SM (32 warps),
// doubling latency coverage vs R4's 2 resident blocks.
// ============================================================
__global__ __launch_bounds__(256, 4) void osc_kernel() {
    __shared__ float s_c[NPAIR * N_PER * 12];  // 48000 B
    for (int i = threadIdx.x; i < NPAIR * N_PER * 3; i += 256)
        ((float4*)s_c)[i] = ((const float4*)g_cpack)[i];
    __syncthreads();

    const int lane = threadIdx.x & 31;
    u64 dt2;
    PACK2(dt2, 0.01f, 0.01f);

    for (;;) {
        unsigned u = 0;
        if (lane == 0) u = atomicAdd(&g_ticket, 1u);
        u = __shfl_sync(0xffffffffu, u, 0);
        if (u >= NUNITS) break;

        const unsigned op = u % NPAIR;
        const unsigned bg = u / NPAIR;
        const int b0 = bg * 64 + lane;
        const int b1 = b0 + 32;

        float4 oA = __ldg((const float4*)(g_x3 + (size_t)b0 * 100 + op * 4));
        float4 oB = __ldg((const float4*)(g_x3 + (size_t)b1 * 100 + op * 4));
        u64 oxa, oya, oxb, oyb;
        PACK2(oxa, oA.x, oA.z);
        PACK2(oya, oA.y, oA.w);
        PACK2(oxb, oB.x, oB.z);
        PACK2(oyb, oB.y, oB.w);

        const ulonglong2* cp = ((const ulonglong2*)s_c) + (size_t)op * 120;
        float* tq_out = g_tqp + (size_t)op * (STEPS * BATCH) + b0;

        for (int t = 0; t < STEPS; ++t) {
            u64 dxa = 0ull, dya = 0ull, tqa = 0ull;
            u64 dxb = 0ull, dyb = 0ull, tqb = 0ull;
#pragma unroll 2
            for (int n = 0; n < N_PER; ++n) {
                ulonglong2 c0 = cp[n * 3 + 0];  // {e0A,e0B | e1A,e1B}
                ulonglong2 c1 = cp[n * 3 + 1];  // {obA,obB | d0A,d0B}
                ulonglong2 c2 = cp[n * 3 + 2];  // {d1A,d1B | wA,wB}
                u64 ta, tb;
                FMA2(ta, oxa, c0.x, c1.x);
                FMA2(tb, oxb, c0.x, c1.x);
                FMA2(ta, oya, c0.y, ta);
                FMA2(tb, oyb, c0.y, tb);
                float l0, h0, l1, h1;
                UNPACK2(l0, h0, ta);
                UNPACK2(l1, h1, tb);
                l0 = fmaxf(l0, 0.f); h0 = fmaxf(h0, 0.f);
                l1 = fmaxf(l1, 0.f); h1 = fmaxf(h1, 0.f);
                u64 aa, ab;
                PACK2(aa, l0, h0);
                PACK2(ab, l1, h1);
                FMA2(dxa, c1.y, aa, dxa);
                FMA2(dxb, c1.y, ab, dxb);
                FMA2(dya, c2.x, aa, dya);
                FMA2(dyb, c2.x, ab, dyb);
                FMA2(tqa, c2.y, aa, tqa);
                FMA2(tqb, c2.y, ab, tqb);
            }
            FMA2(oxa, dt2, dxa, oxa);
            FMA2(oya, dt2, dya, oya);
            FMA2(oxb, dt2, dxb, oxb);
            FMA2(oyb, dt2, dyb, oyb);
            float sl, sh;
            UNPACK2(sl, sh, tqa);
            float s0 = sl + sh;
            UNPACK2(sl, sh, tqb);
            float s1 = sl + sh;
            tq_out[t * BATCH]      = s0;  // b0 slot
            tq_out[t * BATCH + 32] = s1;  // b1 slot
        }
    }
}

// ============================================================
// K4 (pos 5): fused reduce + pendulum scan + output writes
// ============================================================
__global__ void scan_kernel(const float* __restrict__ x,
                            float* __restrict__ out) {
    int b = blockIdx.x * blockDim.x + threadIdx.x;  // < BATCH
    float theta = x[b * 2 + 0];
    float omega = 0.f;
    const float dir = g_dir[b];
    float2* outL = (float2*)out;
    float* outT = out + STEPS * BATCH * 2;
    for (int t = 0; t < STEPS; ++t) {
        float s = 0.f;
        const float* p = g_tqp + (size_t)t * BATCH + b;
#pragma unroll
        for (int q = 0; q < NPAIR; ++q) s += p[(size_t)q * (STEPS * BATCH)];
        float tau = s + dir;
        float alpha = tau - sinf(theta) - 0.1f * omega;  // M_G_LC=1, I=1
        float th2 = theta + 0.01f * omega;
        float om2 = omega + 0.01f * alpha;
        outL[t * BATCH + b] = make_float2(th2, om2);
        outT[t * BATCH + b] = tau;
        theta = th2;
        omega = om2;
    }
}

// ============================================================
extern "C" void kernel_launch(void* const* d_in, const int* in_sizes, int n_in,
                              void* d_out, int out_size) {
    const float* x     = (const float*)d_in[0];
    const float* fc1_w = (const float*)d_in[1];
    const float* fc1_b = (const float*)d_in[2];
    const float* fc2_w = (const float*)d_in[3];
    const float* fc2_b = (const float*)d_in[4];
    const float* fc3_w = (const float*)d_in[5];
    const float* fc3_b = (const float*)d_in[6];
    const float* fcd_w = (const float*)d_in[7];
    const float* fcd_b = (const float*)d_in[8];
    const float* enc   = (const float*)d_in[9];
    const float* obias = (const float*)d_in[10];
    const float* dec   = (const float*)d_in[11];
    const float* fc4_w = (const float*)d_in[12];
    const float* fc4_b = (const float*)d_in[13];
    float* out = (float*)d_out;

    // allow 4 x 48KB blocks per SM (228KB carveout)
    cudaFuncSetAttribute(osc_kernel,
                         cudaFuncAttributePreferredSharedMemoryCarveout, 100);

    prep_kernel<<<128, 256>>>(enc, obias, dec, fc4_w, fc2_w, fc3_w);
    mlp_kernel<<<BATCH / 8, 128>>>(x, fc1_w, fc1_b, fc2_b, fc3_b, fcd_w, fcd_b);
    dir_kernel<<<BATCH / 256, 256>>>(fc4_b);
    osc_kernel<<<592, 256>>>();
    scan_kernel<<<BATCH / 256, 256>>>(x, out);
}

// round 6
// speedup vs baseline: 1.4408x; 1.3004x over previous
#include <cuda_runtime.h>
#include <cuda_bf16.h>
#include <math.h>

typedef unsigned long long u64;

#define N_OSC 50
#define N_PER 40
#define STEPS 100
#define BATCH 8192
#define NPAIR 25               // oscillator pairs
// units: 128 batch-groups of 64 x 25 osc-pairs = 3200 = 400 blocks x 8 warps

// ---------------- packed f32x2 helpers ----------------
#define FMA2(d, a, b, c) \
    asm("fma.rn.f32x2 %0, %1, %2, %3;" : "=l"(d) : "l"(a), "l"(b), "l"(c))
#define PACK2(v, lo, hi) \
    asm("mov.b64 %0, {%1, %2};" : "=l"(v) : "f"(lo), "f"(hi))
#define UNPACK2(lo, hi, v) \
    asm("mov.b64 {%0, %1}, %2;" : "=f"(lo), "=f"(hi) : "l"(v))

// ---------------- device scratch (no allocs allowed) ----------------
__device__ float g_x3[BATCH * 100];            // o0 initial states, [b][100]
__device__ float g_direct[BATCH];              // direct torque term per batch
__device__ float g_dir[BATCH];                 // direct + fc4_b
__device__ float g_cpack[NPAIR * N_PER * 12];  // packed per-(osc-pair, n) constants
__device__ float g_fc2t[128 * 128];            // fc2_w transposed (k-major)
__device__ float g_fc3t[128 * 128];            // fc3_w transposed, zero-padded rows
__device__ float g_tqp[NPAIR * STEPS * BATCH]; // per-osc-pair torque partials

// ============================================================
// K0 (pos 1): pack constants, transpose weights
// layout per (op, n): {e0A,e0B,e1A,e1B, obA,obB,d0A,d0B, d1A,d1B,wA,wB}
// ============================================================
__global__ void prep_kernel(const float* __restrict__ enc,
                            const float* __restrict__ obias,
                            const float* __restrict__ dec,
                            const float* __restrict__ fc4_w,
                            const float* __restrict__ fc2_w,
                            const float* __restrict__ fc3_w) {
    int i = blockIdx.x * blockDim.x + threadIdx.x;
    if (i < 16384) {
        int k = i / 128, j = i % 128;
        g_fc2t[i] = fc2_w[j * 128 + k];
        g_fc3t[i] = (j < 100) ? fc3_w[j * 128 + k] : 0.f;
    }
    if (i < NPAIR * N_PER) {
        int op = i / N_PER, n = i % N_PER;
        int oA = 2 * op, oB = 2 * op + 1;
        float* dst = g_cpack + (size_t)i * 12;
        dst[0]  = enc[oA * 80 + n * 2 + 0];
        dst[1]  = enc[oB * 80 + n * 2 + 0];
        dst[2]  = enc[oA * 80 + n * 2 + 1];
        dst[3]  = enc[oB * 80 + n * 2 + 1];
        dst[4]  = obias[oA * 40 + n];
        dst[5]  = obias[oB * 40 + n];
        dst[6]  = dec[oA * 80 + n];        // dec[oA][0][n]
        dst[7]  = dec[oB * 80 + n];
        dst[8]  = dec[oA * 80 + 40 + n];   // dec[oA][1][n]
        dst[9]  = dec[oB * 80 + 40 + n];
        dst[10] = fc4_w[oA * 40 + n];
        dst[11] = fc4_w[oB * 40 + n];
    }
}

// ============================================================
// K1 (pos 2): MLP. Block = 128 threads = 8 batch rows.
// k-major weights (coalesced LDG.64), all MACs f32x2.
// ============================================================
__global__ __launch_bounds__(128) void mlp_kernel(
    const float* __restrict__ x,
    const float* __restrict__ fc1_w, const float* __restrict__ fc1_b,
    const float* __restrict__ fc2_b, const float* __restrict__ fc3_b,
    const float* __restrict__ fcd_w, const float* __restrict__ fcd_b) {
    __shared__ ulonglong2 s_h[256];
    __shared__ ulonglong2 s_h2[256];
    __shared__ float s_red[4][8];

    const int tid = threadIdx.x;
    const int base = blockIdx.x * 8;

    u64 x0p[4], x1p[4];
#pragma unroll
    for (int p = 0; p < 4; ++p) {
        float2 ra = ((const float2*)x)[base + 2 * p];
        float2 rb = ((const float2*)x)[base + 2 * p + 1];
        PACK2(x0p[p], ra.x, rb.x);
        PACK2(x1p[p], ra.y, rb.y);
    }

    float w0 = fc1_w[tid * 2 + 0], w1 = fc1_w[tid * 2 + 1], b1v = fc1_b[tid];
    u64 w02, w12, b12;
    PACK2(w02, w0, w0);
    PACK2(w12, w1, w1);
    PACK2(b12, b1v, b1v);
    u64 h[4];
    float hr[8];
#pragma unroll
    for (int p = 0; p < 4; ++p) {
        u64 t;
        FMA2(t, w02, x0p[p], b12);
        FMA2(t, w12, x1p[p], t);
        float lo, hi;
        UNPACK2(lo, hi, t);
        lo = fmaxf(lo, 0.f);
        hi = fmaxf(hi, 0.f);
        hr[2 * p] = lo;
        hr[2 * p + 1] = hi;
        PACK2(h[p], lo, hi);
    }
    s_h[tid * 2 + 0] = make_ulonglong2(h[0], h[1]);
    s_h[tid * 2 + 1] = make_ulonglong2(h[2], h[3]);

    {
        float wd = fcd_w[tid];
        int lane = tid & 31, wrp = tid >> 5;
#pragma unroll
        for (int r = 0; r < 8; ++r) {
            float pr = hr[r] * wd;
#pragma unroll
            for (int o = 16; o > 0; o >>= 1) pr += __shfl_down_sync(0xffffffffu, pr, o);
            if (lane == 0) s_red[wrp][r] = pr;
        }
    }
    __syncthreads();
    if (tid < 8)
        g_direct[base + tid] =
            s_red[0][tid] + s_red[1][tid] + s_red[2][tid] + s_red[3][tid] + fcd_b[0];

    const int j0 = (tid & 63) * 2;
    const int rg = tid >> 6;
    u64 a00, a01, a10, a11;
    {
        float ba = fc2_b[j0], bb = fc2_b[j0 + 1];
        PACK2(a00, ba, ba);
        a01 = a00;
        PACK2(a10, bb, bb);
        a11 = a10;
    }
#pragma unroll 4
    for (int k = 0; k < 128; ++k) {
        float2 w = __ldg(((const float2*)(g_fc2t + k * 128)) + (tid & 63));
        u64 wa, wb;
        PACK2(wa, w.x, w.x);
        PACK2(wb, w.y, w.y);
        ulonglong2 hh = s_h[k * 2 + rg];
        FMA2(a00, wa, hh.x, a00);
        FMA2(a01, wa, hh.y, a01);
        FMA2(a10, wb, hh.x, a10);
        FMA2(a11, wb, hh.y, a11);
    }
    {
        float l, hf;
        UNPACK2(l, hf, a00); l = fmaxf(l, 0.f); hf = fmaxf(hf, 0.f); PACK2(a00, l, hf);
        UNPACK2(l, hf, a01); l = fmaxf(l, 0.f); hf = fmaxf(hf, 0.f); PACK2(a01, l, hf);
        UNPACK2(l, hf, a10); l = fmaxf(l, 0.f); hf = fmaxf(hf, 0.f); PACK2(a10, l, hf);
        UNPACK2(l, hf, a11); l = fmaxf(l, 0.f); hf = fmaxf(hf, 0.f); PACK2(a11, l, hf);
    }
    s_h2[j0 * 2 + rg] = make_ulonglong2(a00, a01);
    s_h2[(j0 + 1) * 2 + rg] = make_ulonglong2(a10, a11);
    __syncthreads();

    u64 c00, c01, c10, c11;
    {
        float ba = (j0 < 100) ? fc3_b[j0] : 0.f;
        float bb = (j0 + 1 < 100) ? fc3_b[j0 + 1] : 0.f;
        PACK2(c00, ba, ba);
        c01 = c00;
        PACK2(c10, bb, bb);
        c11 = c10;
    }
#pragma unroll 4
    for (int k = 0; k < 128; ++k) {
        float2 w = __ldg(((const float2*)(g_fc3t + k * 128)) + (tid & 63));
        u64 wa, wb;
        PACK2(wa, w.x, w.x);
        PACK2(wb, w.y, w.y);
        ulonglong2 hh = s_h2[k * 2 + rg];
        FMA2(c00, wa, hh.x, c00);
        FMA2(c01, wa, hh.y, c01);
        FMA2(c10, wb, hh.x, c10);
        FMA2(c11, wb, hh.y, c11);
    }
    {
        float r0, r1, r2, r3;
        if (j0 < 100) {
            UNPACK2(r0, r1, c00);
            UNPACK2(r2, r3, c01);
            g_x3[(size_t)(base + 4 * rg + 0) * 100 + j0] = r0;
            g_x3[(size_t)(base + 4 * rg + 1) * 100 + j0] = r1;
            g_x3[(size_t)(base + 4 * rg + 2) * 100 + j0] = r2;
            g_x3[(size_t)(base + 4 * rg + 3) * 100 + j0] = r3;
        }
        if (j0 + 1 < 100) {
            UNPACK2(r0, r1, c10);
            UNPACK2(r2, r3, c11);
            g_x3[(size_t)(base + 4 * rg + 0) * 100 + j0 + 1] = r0;
            g_x3[(size_t)(base + 4 * rg + 1) * 100 + j0 + 1] = r1;
            g_x3[(size_t)(base + 4 * rg + 2) * 100 + j0 + 1] = r2;
            g_x3[(size_t)(base + 4 * rg + 3) * 100 + j0 + 1] = r3;
        }
    }
}

// ============================================================
// K2 (pos 3): dir = direct + fc4_b (keeps osc at ncu position 4)
// ============================================================
__global__ void dir_kernel(const float* __restrict__ fc4_b) {
    int b = blockIdx.x * blockDim.x + threadIdx.x;
    if (b < BATCH) g_dir[b] = g_direct[b] + fc4_b[0];
}

// ============================================================
// K3 (pos 4): oscillator scan v3 — static schedule, tiny smem.
// grid = 400 blocks x 8 warps = 3200 units (1 per warp, no tail).
// Block b: op = b % 25 (all warps share a 1.92KB constant slice),
// bg = (b/25)*8 + warp. smem drops 48KB -> 1.92KB so occupancy is
// register-limited: 4 blocks/SM = 8 warps/SMSP (was 2 blocks -> 4).
// ============================================================
__global__ __launch_bounds__(256, 4) void osc_kernel() {
    __shared__ float4 s_c[120];  // one osc-pair slice: 40 n x 3 float4
    const unsigned op = blockIdx.x % NPAIR;
    if (threadIdx.x < 120)
        s_c[threadIdx.x] = ((const float4*)g_cpack)[op * 120 + threadIdx.x];
    __syncthreads();

    const int lane = threadIdx.x & 31;
    const int wrp = threadIdx.x >> 5;
    const unsigned bg = (blockIdx.x / NPAIR) * 8 + wrp;
    const int b0 = bg * 64 + lane;
    const int b1 = b0 + 32;

    u64 dt2;
    PACK2(dt2, 0.01f, 0.01f);

    float4 oA = __ldg((const float4*)(g_x3 + (size_t)b0 * 100 + op * 4));
    float4 oB = __ldg((const float4*)(g_x3 + (size_t)b1 * 100 + op * 4));
    u64 oxa, oya, oxb, oyb;
    PACK2(oxa, oA.x, oA.z);
    PACK2(oya, oA.y, oA.w);
    PACK2(oxb, oB.x, oB.z);
    PACK2(oyb, oB.y, oB.w);

    const ulonglong2* cp = (const ulonglong2*)s_c;
    float* tq_out = g_tqp + (size_t)op * (STEPS * BATCH) + b0;

    for (int t = 0; t < STEPS; ++t) {
        u64 dxa = 0ull, dya = 0ull, tqa = 0ull;
        u64 dxb = 0ull, dyb = 0ull, tqb = 0ull;
#pragma unroll 2
        for (int n = 0; n < N_PER; ++n) {
            ulonglong2 c0 = cp[n * 3 + 0];  // {e0A,e0B | e1A,e1B}
            ulonglong2 c1 = cp[n * 3 + 1];  // {obA,obB | d0A,d0B}
            ulonglong2 c2 = cp[n * 3 + 2];  // {d1A,d1B | wA,wB}
            u64 ta, tb;
            FMA2(ta, oxa, c0.x, c1.x);
            FMA2(tb, oxb, c0.x, c1.x);
            FMA2(ta, oya, c0.y, ta);
            FMA2(tb, oyb, c0.y, tb);
            float l0, h0, l1, h1;
            UNPACK2(l0, h0, ta);
            UNPACK2(l1, h1, tb);
            l0 = fmaxf(l0, 0.f); h0 = fmaxf(h0, 0.f);
            l1 = fmaxf(l1, 0.f); h1 = fmaxf(h1, 0.f);
            u64 aa, ab;
            PACK2(aa, l0, h0);
            PACK2(ab, l1, h1);
            FMA2(dxa, c1.y, aa, dxa);
            FMA2(dxb, c1.y, ab, dxb);
            FMA2(dya, c2.x, aa, dya);
            FMA2(dyb, c2.x, ab, dyb);
            FMA2(tqa, c2.y, aa, tqa);
            FMA2(tqb, c2.y, ab, tqb);
        }
        FMA2(oxa, dt2, dxa, oxa);
        FMA2(oya, dt2, dya, oya);
        FMA2(oxb, dt2, dxb, oxb);
        FMA2(oyb, dt2, dyb, oyb);
        float sl, sh;
        UNPACK2(sl, sh, tqa);
        float s0 = sl + sh;
        UNPACK2(sl, sh, tqb);
        float s1 = sl + sh;
        tq_out[t * BATCH]      = s0;  // b0 slot
        tq_out[t * BATCH + 32] = s1;  // b1 slot
    }
}

// ============================================================
// K4 (pos 5): fused reduce + pendulum scan + output writes
// ============================================================
__global__ void scan_kernel(const float* __restrict__ x,
                            float* __restrict__ out) {
    int b = blockIdx.x * blockDim.x + threadIdx.x;  // < BATCH
    float theta = x[b * 2 + 0];
    float omega = 0.f;
    const float dir = g_dir[b];
    float2* outL = (float2*)out;
    float* outT = out + STEPS * BATCH * 2;
    for (int t = 0; t < STEPS; ++t) {
        float s = 0.f;
        const float* p = g_tqp + (size_t)t * BATCH + b;
#pragma unroll
        for (int q = 0; q < NPAIR; ++q) s += p[(size_t)q * (STEPS * BATCH)];
        float tau = s + dir;
        float alpha = tau - sinf(theta) - 0.1f * omega;  // M_G_LC=1, I=1
        float th2 = theta + 0.01f * omega;
        float om2 = omega + 0.01f * alpha;
        outL[t * BATCH + b] = make_float2(th2, om2);
        outT[t * BATCH + b] = tau;
        theta = th2;
        omega = om2;
    }
}

// ============================================================
extern "C" void kernel_launch(void* const* d_in, const int* in_sizes, int n_in,
                              void* d_out, int out_size) {
    const float* x     = (const float*)d_in[0];
    const float* fc1_w = (const float*)d_in[1];
    const float* fc1_b = (const float*)d_in[2];
    const float* fc2_w = (const float*)d_in[3];
    const float* fc2_b = (const float*)d_in[4];
    const float* fc3_w = (const float*)d_in[5];
    const float* fc3_b = (const float*)d_in[6];
    const float* fcd_w = (const float*)d_in[7];
    const float* fcd_b = (const float*)d_in[8];
    const float* enc   = (const float*)d_in[9];
    const float* obias = (const float*)d_in[10];
    const float* dec   = (const float*)d_in[11];
    const float* fc4_w = (const float*)d_in[12];
    const float* fc4_b = (const float*)d_in[13];
    float* out = (float*)d_out;

    prep_kernel<<<128, 256>>>(enc, obias, dec, fc4_w, fc2_w, fc3_w);
    mlp_kernel<<<BATCH / 8, 128>>>(x, fc1_w, fc1_b, fc2_b, fc3_b, fcd_w, fcd_b);
    dir_kernel<<<BATCH / 256, 256>>>(fc4_b);
    osc_kernel<<<400, 256>>>();
    scan_kernel<<<BATCH / 256, 256>>>(x, out);
}